// round 10
// baseline (speedup 1.0000x reference)
#include <cuda_runtime.h>
#include <cuda_bf16.h>
#include <math.h>
#include <stdint.h>

// Problem constants
#define T_TOK 8192
#define HDIM  1024
#define FDIM  3584
#define NEXP  8
#define TOPK  2
#define BM    128
#define ROWS_MAX (T_TOK*TOPK + NEXP*BM)   // 17408
#define OUT_ELEMS (T_TOK*HDIM)

// smem geometry: bf16, 64B rows (32 elems), SW64 swizzle, no padding
#define APL    8192                  // 128 rows * 64 B  (A plane)
#define BPL    8192                  // 128 rows * 64 B  (B plane, BN=128)
#define G1_STAGEB (2*APL + 4*BPL)    // 49152
#define G2_STAGEB (2*APL + 2*BPL)    // 32768
#define G1_STAGES 3
#define G2_STAGES 3
#define SW64B(o) ((o) ^ (((o) >> 3) & 0x30))

#define WELEMS ((size_t)NEXP*FDIM*HDIM)   // 29,360,128

// ---------------- device scratch ----------------
__device__ __nv_bfloat16 g_w1b[WELEMS], g_w1s[WELEMS];
__device__ __nv_bfloat16 g_w3b[WELEMS], g_w3s[WELEMS];
__device__ __nv_bfloat16 g_w2b[WELEMS], g_w2s[WELEMS];
__device__ __nv_bfloat16 g_xb[(size_t)T_TOK*HDIM], g_xs[(size_t)T_TOK*HDIM];
__device__ __nv_bfloat16 g_hb[(size_t)ROWS_MAX*FDIM], g_hs[(size_t)ROWS_MAX*FDIM];
__device__ int   g_row_token[ROWS_MAX];
__device__ float g_row_weight[ROWS_MAX];
__device__ int   g_counts[NEXP];
__device__ int   g_offsets[NEXP + 1];
__device__ int   g_cursor[NEXP];
__device__ int   g_total_rows;
__device__ int   g_tok_expert[T_TOK * TOPK];
__device__ float g_tok_weight[T_TOK * TOPK];

// ---------------- helpers ----------------
__device__ __forceinline__ uint32_t smem_u32(const void* p) {
    uint32_t a;
    asm("{ .reg .u64 t; cvta.to.shared.u64 t, %1; cvt.u32.u64 %0, t; }" : "=r"(a) : "l"(p));
    return a;
}
__device__ __forceinline__ uint32_t pack2(float x, float y) {
    __nv_bfloat162 t = __floats2bfloat162_rn(x, y);
    return *(uint32_t*)&t;
}
__device__ __forceinline__ void split1(float v, float& b, float& s) {
    __nv_bfloat16 hb = __float2bfloat16(v);
    b = __bfloat162float(hb);
    s = v - b;
}
__device__ __forceinline__ void mma16816(float (&d)[4], const uint32_t (&a)[4],
                                         uint32_t b0, uint32_t b1) {
    asm volatile(
        "mma.sync.aligned.m16n8k16.row.col.f32.bf16.bf16.f32 "
        "{%0,%1,%2,%3}, {%4,%5,%6,%7}, {%8,%9}, {%0,%1,%2,%3};"
        : "+f"(d[0]), "+f"(d[1]), "+f"(d[2]), "+f"(d[3])
        : "r"(a[0]), "r"(a[1]), "r"(a[2]), "r"(a[3]), "r"(b0), "r"(b1));
}
__device__ __forceinline__ void ldm4(uint32_t addr, uint32_t (&r)[4]) {
    asm volatile("ldmatrix.sync.aligned.m8n8.x4.shared.b16 {%0,%1,%2,%3}, [%4];"
                 : "=r"(r[0]), "=r"(r[1]), "=r"(r[2]), "=r"(r[3]) : "r"(addr));
}
__device__ __forceinline__ void cpa16(uint32_t dst, const void* src, int sz) {
    asm volatile("cp.async.cg.shared.global [%0], [%1], 16, %2;"
                 :: "r"(dst), "l"(src), "r"(sz) : "memory");
}
#define CP_COMMIT() asm volatile("cp.async.commit_group;" ::: "memory")
#define CP_WAIT1()  asm volatile("cp.async.wait_group 1;" ::: "memory")
#define CP_WAIT0()  asm volatile("cp.async.wait_group 0;" ::: "memory")

// ---------------- 0) init ----------------
__global__ void init_kernel(float* __restrict__ out) {
    int i = blockIdx.x * blockDim.x + threadIdx.x;
    if (i < OUT_ELEMS) out[i] = 0.0f;
    if (i < ROWS_MAX) { g_row_token[i] = -1; g_row_weight[i] = 0.0f; }
    if (i < NEXP) g_counts[i] = 0;
}

// ---------------- 0b) preconvert: fp32 -> bf16 big/small planes ----------------
__global__ void split_w_kernel(const float* __restrict__ w1,
                               const float* __restrict__ w2,
                               const float* __restrict__ w3) {
    int i = blockIdx.x * blockDim.x + threadIdx.x;
    const int N4 = (int)(WELEMS / 4);
    if (i >= N4) return;
    const float* src; __nv_bfloat16 *db, *ds;
    if (blockIdx.y == 0)      { src = w1; db = g_w1b; ds = g_w1s; }
    else if (blockIdx.y == 1) { src = w3; db = g_w3b; ds = g_w3s; }
    else                      { src = w2; db = g_w2b; ds = g_w2s; }
    float4 v = ((const float4*)src)[i];
    float b0,s0,b1,s1,b2,s2,b3,s3;
    split1(v.x,b0,s0); split1(v.y,b1,s1); split1(v.z,b2,s2); split1(v.w,b3,s3);
    ((uint2*)db)[i] = make_uint2(pack2(b0,b1), pack2(b2,b3));
    ((uint2*)ds)[i] = make_uint2(pack2(s0,s1), pack2(s2,s3));
}
__global__ void split_x_kernel(const float* __restrict__ x) {
    int i = blockIdx.x * blockDim.x + threadIdx.x;
    const int N4 = T_TOK * HDIM / 4;
    if (i >= N4) return;
    float4 v = ((const float4*)x)[i];
    float b0,s0,b1,s1,b2,s2,b3,s3;
    split1(v.x,b0,s0); split1(v.y,b1,s1); split1(v.z,b2,s2); split1(v.w,b3,s3);
    ((uint2*)g_xb)[i] = make_uint2(pack2(b0,b1), pack2(b2,b3));
    ((uint2*)g_xs)[i] = make_uint2(pack2(s0,s1), pack2(s2,s3));
}

// ---------------- 1) router ----------------
__global__ void router_kernel(const float* __restrict__ x,
                              const float* __restrict__ gate_w,
                              float* __restrict__ logits_out) {
    __shared__ float s_gate[NEXP * HDIM];
    for (int i = threadIdx.x; i < NEXP * HDIM; i += blockDim.x)
        s_gate[i] = gate_w[i];
    __syncthreads();

    int warp = threadIdx.x >> 5, lane = threadIdx.x & 31;
    int t = blockIdx.x * (blockDim.x >> 5) + warp;
    if (t >= T_TOK) return;

    float acc[NEXP];
#pragma unroll
    for (int e = 0; e < NEXP; e++) acc[e] = 0.0f;
    const float* xr = x + (size_t)t * HDIM;
    for (int j = lane; j < HDIM; j += 32) {
        float xv = xr[j];
#pragma unroll
        for (int e = 0; e < NEXP; e++) acc[e] += xv * s_gate[e * HDIM + j];
    }
#pragma unroll
    for (int e = 0; e < NEXP; e++) {
#pragma unroll
        for (int o = 16; o > 0; o >>= 1)
            acc[e] += __shfl_xor_sync(0xffffffffu, acc[e], o);
    }
    if (lane == 0) {
        float mx = acc[0];
#pragma unroll
        for (int e = 1; e < NEXP; e++) mx = fmaxf(mx, acc[e]);
        float p[NEXP], s = 0.0f;
#pragma unroll
        for (int e = 0; e < NEXP; e++) { p[e] = expf(acc[e] - mx); s += p[e]; }
        float inv = 1.0f / s;
#pragma unroll
        for (int e = 0; e < NEXP; e++) p[e] *= inv;
        int i0 = 0;
#pragma unroll
        for (int e = 1; e < NEXP; e++) if (p[e] > p[i0]) i0 = e;
        int i1 = (i0 == 0) ? 1 : 0;
#pragma unroll
        for (int e = 0; e < NEXP; e++) if (e != i0 && p[e] > p[i1]) i1 = e;
        float w0 = p[i0], w1 = p[i1], ws = 1.0f / (w0 + w1);
        w0 *= ws; w1 *= ws;
#pragma unroll
        for (int e = 0; e < NEXP; e++) logits_out[(size_t)t * NEXP + e] = acc[e];
        g_tok_expert[t * 2 + 0] = i0; g_tok_expert[t * 2 + 1] = i1;
        g_tok_weight[t * 2 + 0] = w0; g_tok_weight[t * 2 + 1] = w1;
        atomicAdd(&g_counts[i0], 1);
        atomicAdd(&g_counts[i1], 1);
    }
}

// ---------------- 2) scan ----------------
__global__ void scan_kernel() {
    int total = 0;
    for (int e = 0; e < NEXP; e++) {
        g_offsets[e] = total;
        g_cursor[e]  = total;
        int padded = ((g_counts[e] + BM - 1) / BM) * BM;
        total += padded;
    }
    g_offsets[NEXP] = total;
    g_total_rows = total;
}

// ---------------- 3) scatter ----------------
__global__ void scatter_kernel() {
    int t = blockIdx.x * blockDim.x + threadIdx.x;
    if (t >= T_TOK) return;
#pragma unroll
    for (int s = 0; s < TOPK; s++) {
        int e = g_tok_expert[t * 2 + s];
        int p = atomicAdd(&g_cursor[e], 1);
        g_row_token[p]  = t;
        g_row_weight[p] = g_tok_weight[t * 2 + s];
    }
}

// ---------------- 4) GEMM1: CTA 128x128, 8 warps 64x32, 3-stage, bf16x3 --------
__global__ __launch_bounds__(256, 1)
void gemm1_mma() {
    int row0 = blockIdx.x * BM;
    if (row0 >= g_total_rows) return;
    int n0 = blockIdx.y * 128;

    int e = 0;
#pragma unroll
    for (int i = 0; i < NEXP; i++) if (row0 >= g_offsets[i + 1]) e = i + 1;

    extern __shared__ char smem[];
    uint32_t sb = smem_u32(smem);
    int tid = threadIdx.x, wid = tid >> 5, lane = tid & 31;
    int wm = wid & 1, wn = wid >> 1;          // warp tile 64x32 on 128x128 CTA

    const __nv_bfloat16* bsrc[4] = {
        g_w1b + (size_t)e * FDIM * HDIM, g_w1s + (size_t)e * FDIM * HDIM,
        g_w3b + (size_t)e * FDIM * HDIM, g_w3s + (size_t)e * FDIM * HDIM };

    int tokc[4];
#pragma unroll
    for (int i = 0; i < 4; i++) tokc[i] = g_row_token[row0 + ((tid + i * 256) >> 3)];

    float acc1[4][4][4], acc3[4][4][4];
#pragma unroll
    for (int m = 0; m < 4; m++)
#pragma unroll
        for (int j = 0; j < 4; j++)
#pragma unroll
            for (int q = 0; q < 4; q++) { acc1[m][j][q] = 0.0f; acc3[m][j][q] = 0.0f; }

    const int NC = HDIM / 32;

    int r8 = lane & 7;
    uint32_t rowA_l = (uint32_t)(((lane >> 3) & 1) * 8 + r8);
    uint32_t kAb    = (uint32_t)(((lane >> 4) & 1) * 16);   // byte offset
    uint32_t nB_l   = (uint32_t)(((lane >> 4) & 1) * 8 + r8);
    uint32_t kBb    = (uint32_t)(((lane >> 3) & 1) * 16);

    auto loadg = [&](int cn) {
        int k0 = cn * 32;
        uint32_t st = sb + (cn % G1_STAGES) * G1_STAGEB;
#pragma unroll
        for (int i = 0; i < 4; i++) {       // A: 2 planes x 128 rows x 4
            int idx = tid + i * 256;
            int c16 = idx & 3, plane = (idx >> 2) & 1, row = idx >> 3;
            uint32_t dst = st + plane * APL + SW64B((uint32_t)(row * 64 + c16 * 16));
            int t = tokc[i];
            const __nv_bfloat16* src = (plane ? g_xs : g_xb)
                + ((size_t)(t < 0 ? 0 : t) * HDIM + k0 + c16 * 8);
            cpa16(dst, src, t < 0 ? 0 : 16);
        }
#pragma unroll
        for (int i = 0; i < 8; i++) {       // B: 4 planes x 128 rows x 4
            int idx = tid + i * 256;
            int c16 = idx & 3, plane = (idx >> 2) & 3, row = idx >> 4;
            uint32_t dst = st + 2 * APL + plane * BPL + SW64B((uint32_t)(row * 64 + c16 * 16));
            cpa16(dst, bsrc[plane] + ((size_t)(n0 + row) * HDIM + k0 + c16 * 8), 16);
        }
        CP_COMMIT();
    };

    loadg(0); loadg(1);
    for (int c = 0; c < NC; c++) {
        if (c + 2 < NC) { CP_WAIT1(); } else { CP_WAIT0(); }
        __syncthreads();
        if (c + 2 < NC) loadg(c + 2);
        uint32_t st = sb + (c % G1_STAGES) * G1_STAGEB;
#pragma unroll
        for (int kk = 0; kk < 2; kk++) {
            uint32_t Ab[4][4], As[4][4];
#pragma unroll
            for (int mb = 0; mb < 4; mb++) {
                uint32_t off = SW64B((uint32_t)((wm * 64 + mb * 16 + rowA_l) * 64 + kk * 32 + kAb));
                ldm4(st + off, Ab[mb]);
                ldm4(st + APL + off, As[mb]);
            }
#pragma unroll
            for (int jp = 0; jp < 2; jp++) {
                uint32_t boff = SW64B((uint32_t)((wn * 32 + jp * 16 + nB_l) * 64 + kk * 32 + kBb));
                uint32_t bb = st + 2 * APL + boff;
                uint32_t B1b[4], B1s[4], B3b[4], B3s[4];
                ldm4(bb,           B1b);
                ldm4(bb + BPL,     B1s);
                ldm4(bb + 2 * BPL, B3b);
                ldm4(bb + 3 * BPL, B3s);
                int j0 = jp * 2;
#pragma unroll
                for (int mb = 0; mb < 4; mb++) {
                    mma16816(acc1[mb][j0],   Ab[mb], B1b[0], B1b[1]);
                    mma16816(acc1[mb][j0+1], Ab[mb], B1b[2], B1b[3]);
                    mma16816(acc3[mb][j0],   Ab[mb], B3b[0], B3b[1]);
                    mma16816(acc3[mb][j0+1], Ab[mb], B3b[2], B3b[3]);
                }
#pragma unroll
                for (int mb = 0; mb < 4; mb++) {
                    mma16816(acc1[mb][j0],   Ab[mb], B1s[0], B1s[1]);
                    mma16816(acc1[mb][j0+1], Ab[mb], B1s[2], B1s[3]);
                    mma16816(acc3[mb][j0],   Ab[mb], B3s[0], B3s[1]);
                    mma16816(acc3[mb][j0+1], Ab[mb], B3s[2], B3s[3]);
                }
#pragma unroll
                for (int mb = 0; mb < 4; mb++) {
                    mma16816(acc1[mb][j0],   As[mb], B1b[0], B1b[1]);
                    mma16816(acc1[mb][j0+1], As[mb], B1b[2], B1b[3]);
                    mma16816(acc3[mb][j0],   As[mb], B3b[0], B3b[1]);
                    mma16816(acc3[mb][j0+1], As[mb], B3b[2], B3b[3]);
                }
            }
        }
    }

    // epilogue: h = silu(g)*u -> big/small planes
#pragma unroll
    for (int mb = 0; mb < 4; mb++) {
        int rA = row0 + wm * 64 + mb * 16 + (lane >> 2);
        int rB = rA + 8;
#pragma unroll
        for (int j = 0; j < 4; j++) {
            int col = n0 + wn * 32 + j * 8 + (lane & 3) * 2;
            float g0 = acc1[mb][j][0], g1 = acc1[mb][j][1];
            float g2 = acc1[mb][j][2], g3 = acc1[mb][j][3];
            float u0 = acc3[mb][j][0], u1 = acc3[mb][j][1];
            float u2 = acc3[mb][j][2], u3 = acc3[mb][j][3];
            float h0 = g0 / (1.0f + __expf(-g0)) * u0;
            float h1 = g1 / (1.0f + __expf(-g1)) * u1;
            float h2 = g2 / (1.0f + __expf(-g2)) * u2;
            float h3 = g3 / (1.0f + __expf(-g3)) * u3;
            float b0,s0,b1,s1;
            split1(h0, b0, s0); split1(h1, b1, s1);
            *(uint32_t*)(g_hb + (size_t)rA * FDIM + col) = pack2(b0, b1);
            *(uint32_t*)(g_hs + (size_t)rA * FDIM + col) = pack2(s0, s1);
            split1(h2, b0, s0); split1(h3, b1, s1);
            *(uint32_t*)(g_hb + (size_t)rB * FDIM + col) = pack2(b0, b1);
            *(uint32_t*)(g_hs + (size_t)rB * FDIM + col) = pack2(s0, s1);
        }
    }
}

// ---------------- 5) GEMM2: CTA 128x128, 8 warps 64x32, 3-stage, bf16x3 --------
__global__ __launch_bounds__(256, 2)
void gemm2_mma(float* __restrict__ out) {
    int row0 = blockIdx.x * BM;
    if (row0 >= g_total_rows) return;
    int n0 = blockIdx.y * 128;

    int e = 0;
#pragma unroll
    for (int i = 0; i < NEXP; i++) if (row0 >= g_offsets[i + 1]) e = i + 1;

    extern __shared__ char smem[];
    uint32_t sb = smem_u32(smem);
    int tid = threadIdx.x, wid = tid >> 5, lane = tid & 31;
    int wm = wid & 1, wn = wid >> 1;

    const __nv_bfloat16* w2b_e = g_w2b + (size_t)e * HDIM * FDIM;
    const __nv_bfloat16* w2s_e = g_w2s + (size_t)e * HDIM * FDIM;

    float acc[4][4][4];
#pragma unroll
    for (int m = 0; m < 4; m++)
#pragma unroll
        for (int j = 0; j < 4; j++)
#pragma unroll
            for (int q = 0; q < 4; q++) acc[m][j][q] = 0.0f;

    const int NC = FDIM / 32;

    int r8 = lane & 7;
    uint32_t rowA_l = (uint32_t)(((lane >> 3) & 1) * 8 + r8);
    uint32_t kAb    = (uint32_t)(((lane >> 4) & 1) * 16);
    uint32_t nB_l   = (uint32_t)(((lane >> 4) & 1) * 8 + r8);
    uint32_t kBb    = (uint32_t)(((lane >> 3) & 1) * 16);

    auto loadg = [&](int cn) {
        int k0 = cn * 32;
        uint32_t st = sb + (cn % G2_STAGES) * G2_STAGEB;
#pragma unroll
        for (int i = 0; i < 4; i++) {       // A: 2 planes x 128 rows x 4
            int idx = tid + i * 256;
            int c16 = idx & 3, plane = (idx >> 2) & 1, row = idx >> 3;
            uint32_t dst = st + plane * APL + SW64B((uint32_t)(row * 64 + c16 * 16));
            const __nv_bfloat16* src = (plane ? g_hs : g_hb)
                + ((size_t)(row0 + row) * FDIM + k0 + c16 * 8);
            cpa16(dst, src, 16);
        }
#pragma unroll
        for (int i = 0; i < 4; i++) {       // B: 2 planes x 128 rows x 4
            int idx = tid + i * 256;
            int c16 = idx & 3, plane = (idx >> 2) & 1, row = idx >> 3;
            uint32_t dst = st + 2 * APL + plane * BPL + SW64B((uint32_t)(row * 64 + c16 * 16));
            const __nv_bfloat16* src = (plane ? w2s_e : w2b_e)
                + ((size_t)(n0 + row) * FDIM + k0 + c16 * 8);
            cpa16(dst, src, 16);
        }
        CP_COMMIT();
    };

    loadg(0); loadg(1);
    for (int c = 0; c < NC; c++) {
        if (c + 2 < NC) { CP_WAIT1(); } else { CP_WAIT0(); }
        __syncthreads();
        if (c + 2 < NC) loadg(c + 2);
        uint32_t st = sb + (c % G2_STAGES) * G2_STAGEB;
#pragma unroll
        for (int kk = 0; kk < 2; kk++) {
            uint32_t Ab[4][4], As[4][4];
#pragma unroll
            for (int mb = 0; mb < 4; mb++) {
                uint32_t off = SW64B((uint32_t)((wm * 64 + mb * 16 + rowA_l) * 64 + kk * 32 + kAb));
                ldm4(st + off, Ab[mb]);
                ldm4(st + APL + off, As[mb]);
            }
#pragma unroll
            for (int jp = 0; jp < 2; jp++) {
                uint32_t boff = SW64B((uint32_t)((wn * 32 + jp * 16 + nB_l) * 64 + kk * 32 + kBb));
                uint32_t bb = st + 2 * APL + boff;
                uint32_t Bb[4], Bs[4];
                ldm4(bb,       Bb);
                ldm4(bb + BPL, Bs);
                int j0 = jp * 2;
#pragma unroll
                for (int mb = 0; mb < 4; mb++) {
                    mma16816(acc[mb][j0],   Ab[mb], Bb[0], Bb[1]);
                    mma16816(acc[mb][j0+1], Ab[mb], Bb[2], Bb[3]);
                }
#pragma unroll
                for (int mb = 0; mb < 4; mb++) {
                    mma16816(acc[mb][j0],   Ab[mb], Bs[0], Bs[1]);
                    mma16816(acc[mb][j0+1], Ab[mb], Bs[2], Bs[3]);
                }
#pragma unroll
                for (int mb = 0; mb < 4; mb++) {
                    mma16816(acc[mb][j0],   As[mb], Bb[0], Bb[1]);
                    mma16816(acc[mb][j0+1], As[mb], Bb[2], Bb[3]);
                }
            }
        }
    }

    // epilogue: weighted atomicAdd
#pragma unroll
    for (int mb = 0; mb < 4; mb++) {
        int rA = row0 + wm * 64 + mb * 16 + (lane >> 2);
        int rB = rA + 8;
        int tA = g_row_token[rA], tB = g_row_token[rB];
        float wA = g_row_weight[rA], wB = g_row_weight[rB];
#pragma unroll
        for (int j = 0; j < 4; j++) {
            int col = n0 + wn * 32 + j * 8 + (lane & 3) * 2;
            if (tA >= 0) {
                float* p = out + (size_t)tA * HDIM + col;
                atomicAdd(p + 0, acc[mb][j][0] * wA);
                atomicAdd(p + 1, acc[mb][j][1] * wA);
            }
            if (tB >= 0) {
                float* p = out + (size_t)tB * HDIM + col;
                atomicAdd(p + 0, acc[mb][j][2] * wB);
                atomicAdd(p + 1, acc[mb][j][3] * wB);
            }
        }
    }
}

// ---------------- launcher ----------------
extern "C" void kernel_launch(void* const* d_in, const int* in_sizes, int n_in,
                              void* d_out, int out_size) {
    const float* x      = (const float*)d_in[0];
    const float* gate_w = (const float*)d_in[1];
    const float* w1     = (const float*)d_in[2];
    const float* w2     = (const float*)d_in[3];
    const float* w3     = (const float*)d_in[4];
    float* out          = (float*)d_out;
    float* logits_out   = out + (size_t)OUT_ELEMS;
    (void)in_sizes; (void)n_in; (void)out_size;

    const int smem1 = G1_STAGES * G1_STAGEB;   // 147456
    const int smem2 = G2_STAGES * G2_STAGEB;   // 98304
    cudaFuncSetAttribute(gemm1_mma, cudaFuncAttributeMaxDynamicSharedMemorySize, smem1);
    cudaFuncSetAttribute(gemm2_mma, cudaFuncAttributeMaxDynamicSharedMemorySize, smem2);

    init_kernel<<<(OUT_ELEMS + 255) / 256, 256>>>(out);
    {
        int n4w = (int)(WELEMS / 4);
        dim3 gw((n4w + 255) / 256, 3);
        split_w_kernel<<<gw, 256>>>(w1, w2, w3);
        split_x_kernel<<<(T_TOK * HDIM / 4 + 255) / 256, 256>>>(x);
    }
    router_kernel<<<T_TOK / 8, 256>>>(x, gate_w, logits_out);
    scan_kernel<<<1, 1>>>();
    scatter_kernel<<<(T_TOK + 255) / 256, 256>>>();

    dim3 g1(ROWS_MAX / BM, FDIM / 128);
    gemm1_mma<<<g1, 256, smem1>>>();
    dim3 g2(ROWS_MAX / BM, HDIM / 128);
    gemm2_mma<<<g2, 256, smem2>>>(out);
}

// round 14
// speedup vs baseline: 1.0548x; 1.0548x over previous
#include <cuda_runtime.h>
#include <cuda_bf16.h>
#include <math.h>
#include <stdint.h>

// Problem constants
#define T_TOK 8192
#define HDIM  1024
#define FDIM  3584
#define NEXP  8
#define TOPK  2
#define BM    128
#define ROWS_MAX (T_TOK*TOPK + NEXP*BM)   // 17408
#define OUT_ELEMS (T_TOK*HDIM)

// smem geometry: bf16, 64B rows (32 elems), SW64 swizzle, no padding
#define APL    8192                  // 128 rows * 64 B  (one A plane)
#define BPL    4096                  // 64 rows * 64 B   (one B plane)
#define G1_STAGEB (2*APL + 4*BPL)    // 32768
#define G2_STAGEB (2*APL + 2*BPL)    // 24576
#define G1_STAGES 3
#define G2_STAGES 4
#define SW64B(o) ((o) ^ (((o) >> 3) & 0x30))

// grid swizzle params
#define G1_NN (FDIM/64)              // 56 n-tiles
#define G1_GRP 4                     // m-tiles per group
#define G2_NN (HDIM/64)              // 16 n-tiles
#define G2_GRP 8

#define WELEMS ((size_t)NEXP*FDIM*HDIM)   // 29,360,128

// ---------------- device scratch ----------------
__device__ __nv_bfloat16 g_w1b[WELEMS], g_w1s[WELEMS];
__device__ __nv_bfloat16 g_w3b[WELEMS], g_w3s[WELEMS];
__device__ __nv_bfloat16 g_w2b[WELEMS], g_w2s[WELEMS];
__device__ __nv_bfloat16 g_xb[(size_t)T_TOK*HDIM], g_xs[(size_t)T_TOK*HDIM];
__device__ __nv_bfloat16 g_hb[(size_t)ROWS_MAX*FDIM], g_hs[(size_t)ROWS_MAX*FDIM];
__device__ int   g_row_token[ROWS_MAX];
__device__ float g_row_weight[ROWS_MAX];
__device__ int   g_counts[NEXP];
__device__ int   g_offsets[NEXP + 1];
__device__ int   g_cursor[NEXP];
__device__ int   g_total_rows;
__device__ int   g_tok_expert[T_TOK * TOPK];
__device__ float g_tok_weight[T_TOK * TOPK];

// ---------------- helpers ----------------
__device__ __forceinline__ uint32_t smem_u32(const void* p) {
    uint32_t a;
    asm("{ .reg .u64 t; cvta.to.shared.u64 t, %1; cvt.u32.u64 %0, t; }" : "=r"(a) : "l"(p));
    return a;
}
__device__ __forceinline__ uint32_t pack2(float x, float y) {
    __nv_bfloat162 t = __floats2bfloat162_rn(x, y);
    return *(uint32_t*)&t;
}
__device__ __forceinline__ void split1(float v, float& b, float& s) {
    __nv_bfloat16 hb = __float2bfloat16(v);
    b = __bfloat162float(hb);
    s = v - b;
}
__device__ __forceinline__ void mma16816(float (&d)[4], const uint32_t (&a)[4],
                                         uint32_t b0, uint32_t b1) {
    asm volatile(
        "mma.sync.aligned.m16n8k16.row.col.f32.bf16.bf16.f32 "
        "{%0,%1,%2,%3}, {%4,%5,%6,%7}, {%8,%9}, {%0,%1,%2,%3};"
        : "+f"(d[0]), "+f"(d[1]), "+f"(d[2]), "+f"(d[3])
        : "r"(a[0]), "r"(a[1]), "r"(a[2]), "r"(a[3]), "r"(b0), "r"(b1));
}
__device__ __forceinline__ void ldm4(uint32_t addr, uint32_t (&r)[4]) {
    asm volatile("ldmatrix.sync.aligned.m8n8.x4.shared.b16 {%0,%1,%2,%3}, [%4];"
                 : "=r"(r[0]), "=r"(r[1]), "=r"(r[2]), "=r"(r[3]) : "r"(addr));
}
__device__ __forceinline__ void cpa16(uint32_t dst, const void* src, int sz) {
    asm volatile("cp.async.cg.shared.global [%0], [%1], 16, %2;"
                 :: "r"(dst), "l"(src), "r"(sz) : "memory");
}
#define CP_COMMIT() asm volatile("cp.async.commit_group;" ::: "memory")
#define CP_WAIT2()  asm volatile("cp.async.wait_group 2;" ::: "memory")
#define CP_WAIT1()  asm volatile("cp.async.wait_group 1;" ::: "memory")
#define CP_WAIT0()  asm volatile("cp.async.wait_group 0;" ::: "memory")

// ---------------- 0) init ----------------
__global__ void init_kernel(float* __restrict__ out) {
    int i = blockIdx.x * blockDim.x + threadIdx.x;
    if (i < OUT_ELEMS) out[i] = 0.0f;
    if (i < ROWS_MAX) { g_row_token[i] = -1; g_row_weight[i] = 0.0f; }
    if (i < NEXP) g_counts[i] = 0;
}

// ---------------- 0b) preconvert: fp32 -> bf16 big/small planes ----------------
__global__ void split_w_kernel(const float* __restrict__ w1,
                               const float* __restrict__ w2,
                               const float* __restrict__ w3) {
    int i = blockIdx.x * blockDim.x + threadIdx.x;
    const int N4 = (int)(WELEMS / 4);
    if (i >= N4) return;
    const float* src; __nv_bfloat16 *db, *ds;
    if (blockIdx.y == 0)      { src = w1; db = g_w1b; ds = g_w1s; }
    else if (blockIdx.y == 1) { src = w3; db = g_w3b; ds = g_w3s; }
    else                      { src = w2; db = g_w2b; ds = g_w2s; }
    float4 v = ((const float4*)src)[i];
    float b0,s0,b1,s1,b2,s2,b3,s3;
    split1(v.x,b0,s0); split1(v.y,b1,s1); split1(v.z,b2,s2); split1(v.w,b3,s3);
    ((uint2*)db)[i] = make_uint2(pack2(b0,b1), pack2(b2,b3));
    ((uint2*)ds)[i] = make_uint2(pack2(s0,s1), pack2(s2,s3));
}
__global__ void split_x_kernel(const float* __restrict__ x) {
    int i = blockIdx.x * blockDim.x + threadIdx.x;
    const int N4 = T_TOK * HDIM / 4;
    if (i >= N4) return;
    float4 v = ((const float4*)x)[i];
    float b0,s0,b1,s1,b2,s2,b3,s3;
    split1(v.x,b0,s0); split1(v.y,b1,s1); split1(v.z,b2,s2); split1(v.w,b3,s3);
    ((uint2*)g_xb)[i] = make_uint2(pack2(b0,b1), pack2(b2,b3));
    ((uint2*)g_xs)[i] = make_uint2(pack2(s0,s1), pack2(s2,s3));
}

// ---------------- 1) router ----------------
__global__ void router_kernel(const float* __restrict__ x,
                              const float* __restrict__ gate_w,
                              float* __restrict__ logits_out) {
    __shared__ float s_gate[NEXP * HDIM];
    for (int i = threadIdx.x; i < NEXP * HDIM; i += blockDim.x)
        s_gate[i] = gate_w[i];
    __syncthreads();

    int warp = threadIdx.x >> 5, lane = threadIdx.x & 31;
    int t = blockIdx.x * (blockDim.x >> 5) + warp;
    if (t >= T_TOK) return;

    float acc[NEXP];
#pragma unroll
    for (int e = 0; e < NEXP; e++) acc[e] = 0.0f;
    const float* xr = x + (size_t)t * HDIM;
    for (int j = lane; j < HDIM; j += 32) {
        float xv = xr[j];
#pragma unroll
        for (int e = 0; e < NEXP; e++) acc[e] += xv * s_gate[e * HDIM + j];
    }
#pragma unroll
    for (int e = 0; e < NEXP; e++) {
#pragma unroll
        for (int o = 16; o > 0; o >>= 1)
            acc[e] += __shfl_xor_sync(0xffffffffu, acc[e], o);
    }
    if (lane == 0) {
        float mx = acc[0];
#pragma unroll
        for (int e = 1; e < NEXP; e++) mx = fmaxf(mx, acc[e]);
        float p[NEXP], s = 0.0f;
#pragma unroll
        for (int e = 0; e < NEXP; e++) { p[e] = expf(acc[e] - mx); s += p[e]; }
        float inv = 1.0f / s;
#pragma unroll
        for (int e = 0; e < NEXP; e++) p[e] *= inv;
        int i0 = 0;
#pragma unroll
        for (int e = 1; e < NEXP; e++) if (p[e] > p[i0]) i0 = e;
        int i1 = (i0 == 0) ? 1 : 0;
#pragma unroll
        for (int e = 0; e < NEXP; e++) if (e != i0 && p[e] > p[i1]) i1 = e;
        float w0 = p[i0], w1 = p[i1], ws = 1.0f / (w0 + w1);
        w0 *= ws; w1 *= ws;
#pragma unroll
        for (int e = 0; e < NEXP; e++) logits_out[(size_t)t * NEXP + e] = acc[e];
        g_tok_expert[t * 2 + 0] = i0; g_tok_expert[t * 2 + 1] = i1;
        g_tok_weight[t * 2 + 0] = w0; g_tok_weight[t * 2 + 1] = w1;
        atomicAdd(&g_counts[i0], 1);
        atomicAdd(&g_counts[i1], 1);
    }
}

// ---------------- 2) scan ----------------
__global__ void scan_kernel() {
    int total = 0;
    for (int e = 0; e < NEXP; e++) {
        g_offsets[e] = total;
        g_cursor[e]  = total;
        int padded = ((g_counts[e] + BM - 1) / BM) * BM;
        total += padded;
    }
    g_offsets[NEXP] = total;
    g_total_rows = total;
}

// ---------------- 3) scatter ----------------
__global__ void scatter_kernel() {
    int t = blockIdx.x * blockDim.x + threadIdx.x;
    if (t >= T_TOK) return;
#pragma unroll
    for (int s = 0; s < TOPK; s++) {
        int e = g_tok_expert[t * 2 + s];
        int p = atomicAdd(&g_cursor[e], 1);
        g_row_token[p]  = t;
        g_row_weight[p] = g_tok_weight[t * 2 + s];
    }
}

// ---------------- 4) GEMM1: 4 warps 64x32, 3-stage cp.async, bf16x3 ------------
// L2-aware swizzled grid: groups of G1_GRP m-tiles x all n-tiles, m fastest.
__global__ __launch_bounds__(128, 2)
void gemm1_mma() {
    // decode swizzled linear index
    int idx = blockIdx.x;
    const int per_group = G1_GRP * G1_NN;
    int grp = idx / per_group;
    int rem = idx - grp * per_group;
    int n_i = rem / G1_GRP;
    int m_i = grp * G1_GRP + (rem - n_i * G1_GRP);
    int row0 = m_i * BM;
    if (row0 >= g_total_rows) return;
    int n0 = n_i * 64;

    int e = 0;
#pragma unroll
    for (int i = 0; i < NEXP; i++) if (row0 >= g_offsets[i + 1]) e = i + 1;

    extern __shared__ char smem[];
    uint32_t sb = smem_u32(smem);
    int tid = threadIdx.x, wid = tid >> 5, lane = tid & 31;
    int wm = wid & 1, wn = wid >> 1;          // warp 64x32 on 128x64 CTA

    const __nv_bfloat16* bsrc[4] = {
        g_w1b + (size_t)e * FDIM * HDIM, g_w1s + (size_t)e * FDIM * HDIM,
        g_w3b + (size_t)e * FDIM * HDIM, g_w3s + (size_t)e * FDIM * HDIM };

    int tokc[8];
#pragma unroll
    for (int i = 0; i < 8; i++) tokc[i] = g_row_token[row0 + ((tid + i * 128) >> 3)];

    float acc1[4][4][4], acc3[4][4][4];
#pragma unroll
    for (int m = 0; m < 4; m++)
#pragma unroll
        for (int j = 0; j < 4; j++)
#pragma unroll
            for (int q = 0; q < 4; q++) { acc1[m][j][q] = 0.0f; acc3[m][j][q] = 0.0f; }

    const int NC = HDIM / 32;

    int r8 = lane & 7;
    uint32_t rowA_l = (uint32_t)(((lane >> 3) & 1) * 8 + r8);
    uint32_t kAb    = (uint32_t)(((lane >> 4) & 1) * 16);   // byte offset
    uint32_t nB_l   = (uint32_t)(((lane >> 4) & 1) * 8 + r8);
    uint32_t kBb    = (uint32_t)(((lane >> 3) & 1) * 16);

    auto loadg = [&](int cn) {
        int k0 = cn * 32;
        uint32_t st = sb + (cn % G1_STAGES) * G1_STAGEB;
#pragma unroll
        for (int i = 0; i < 8; i++) {       // A: 2 planes x 128 rows x 4
            int idx2 = tid + i * 128;
            int c16 = idx2 & 3, plane = (idx2 >> 2) & 1, row = idx2 >> 3;
            uint32_t dst = st + plane * APL + SW64B((uint32_t)(row * 64 + c16 * 16));
            int t = tokc[i];
            const __nv_bfloat16* src = (plane ? g_xs : g_xb)
                + ((size_t)(t < 0 ? 0 : t) * HDIM + k0 + c16 * 8);
            cpa16(dst, src, t < 0 ? 0 : 16);
        }
#pragma unroll
        for (int i = 0; i < 8; i++) {       // B: 4 planes x 64 rows x 4
            int idx2 = tid + i * 128;
            int c16 = idx2 & 3, plane = (idx2 >> 2) & 3, row = idx2 >> 4;
            uint32_t dst = st + 2 * APL + plane * BPL + SW64B((uint32_t)(row * 64 + c16 * 16));
            cpa16(dst, bsrc[plane] + ((size_t)(n0 + row) * HDIM + k0 + c16 * 8), 16);
        }
        CP_COMMIT();
    };

    loadg(0); loadg(1);
    for (int c = 0; c < NC; c++) {
        if (c + 2 < NC) { CP_WAIT1(); } else { CP_WAIT0(); }
        __syncthreads();
        if (c + 2 < NC) loadg(c + 2);
        uint32_t st = sb + (c % G1_STAGES) * G1_STAGEB;
#pragma unroll
        for (int kk = 0; kk < 2; kk++) {
            uint32_t Ab[4][4], As[4][4];
#pragma unroll
            for (int mb = 0; mb < 4; mb++) {
                uint32_t off = SW64B((uint32_t)((wm * 64 + mb * 16 + rowA_l) * 64 + kk * 32 + kAb));
                ldm4(st + off, Ab[mb]);
                ldm4(st + APL + off, As[mb]);
            }
#pragma unroll
            for (int jp = 0; jp < 2; jp++) {
                uint32_t boff = SW64B((uint32_t)((wn * 32 + jp * 16 + nB_l) * 64 + kk * 32 + kBb));
                uint32_t bb = st + 2 * APL + boff;
                uint32_t B1b[4], B1s[4], B3b[4], B3s[4];
                ldm4(bb,           B1b);
                ldm4(bb + BPL,     B1s);
                ldm4(bb + 2 * BPL, B3b);
                ldm4(bb + 3 * BPL, B3s);
                int j0 = jp * 2;
#pragma unroll
                for (int mb = 0; mb < 4; mb++) {
                    mma16816(acc1[mb][j0],   Ab[mb], B1b[0], B1b[1]);
                    mma16816(acc1[mb][j0+1], Ab[mb], B1b[2], B1b[3]);
                    mma16816(acc3[mb][j0],   Ab[mb], B3b[0], B3b[1]);
                    mma16816(acc3[mb][j0+1], Ab[mb], B3b[2], B3b[3]);
                }
#pragma unroll
                for (int mb = 0; mb < 4; mb++) {
                    mma16816(acc1[mb][j0],   Ab[mb], B1s[0], B1s[1]);
                    mma16816(acc1[mb][j0+1], Ab[mb], B1s[2], B1s[3]);
                    mma16816(acc3[mb][j0],   Ab[mb], B3s[0], B3s[1]);
                    mma16816(acc3[mb][j0+1], Ab[mb], B3s[2], B3s[3]);
                }
#pragma unroll
                for (int mb = 0; mb < 4; mb++) {
                    mma16816(acc1[mb][j0],   As[mb], B1b[0], B1b[1]);
                    mma16816(acc1[mb][j0+1], As[mb], B1b[2], B1b[3]);
                    mma16816(acc3[mb][j0],   As[mb], B3b[0], B3b[1]);
                    mma16816(acc3[mb][j0+1], As[mb], B3b[2], B3b[3]);
                }
            }
        }
    }

    // epilogue: h = silu(g)*u -> big/small planes
#pragma unroll
    for (int mb = 0; mb < 4; mb++) {
        int rA = row0 + wm * 64 + mb * 16 + (lane >> 2);
        int rB = rA + 8;
#pragma unroll
        for (int j = 0; j < 4; j++) {
            int col = n0 + wn * 32 + j * 8 + (lane & 3) * 2;
            float g0 = acc1[mb][j][0], g1 = acc1[mb][j][1];
            float g2 = acc1[mb][j][2], g3 = acc1[mb][j][3];
            float u0 = acc3[mb][j][0], u1 = acc3[mb][j][1];
            float u2 = acc3[mb][j][2], u3 = acc3[mb][j][3];
            float h0 = g0 / (1.0f + __expf(-g0)) * u0;
            float h1 = g1 / (1.0f + __expf(-g1)) * u1;
            float h2 = g2 / (1.0f + __expf(-g2)) * u2;
            float h3 = g3 / (1.0f + __expf(-g3)) * u3;
            float b0,s0,b1,s1;
            split1(h0, b0, s0); split1(h1, b1, s1);
            *(uint32_t*)(g_hb + (size_t)rA * FDIM + col) = pack2(b0, b1);
            *(uint32_t*)(g_hs + (size_t)rA * FDIM + col) = pack2(s0, s1);
            split1(h2, b0, s0); split1(h3, b1, s1);
            *(uint32_t*)(g_hb + (size_t)rB * FDIM + col) = pack2(b0, b1);
            *(uint32_t*)(g_hs + (size_t)rB * FDIM + col) = pack2(s0, s1);
        }
    }
}

// ---------------- 5) GEMM2: 4 warps 64x32, 4-stage cp.async, bf16x3 ------------
// L2-aware swizzled grid: groups of G2_GRP m-tiles x all 16 n-tiles, m fastest.
__global__ __launch_bounds__(128, 2)
void gemm2_mma(float* __restrict__ out) {
    int idx = blockIdx.x;
    const int per_group = G2_GRP * G2_NN;
    int grp = idx / per_group;
    int rem = idx - grp * per_group;
    int n_i = rem / G2_GRP;
    int m_i = grp * G2_GRP + (rem - n_i * G2_GRP);
    int row0 = m_i * BM;
    if (row0 >= g_total_rows) return;
    int n0 = n_i * 64;

    int e = 0;
#pragma unroll
    for (int i = 0; i < NEXP; i++) if (row0 >= g_offsets[i + 1]) e = i + 1;

    extern __shared__ char smem[];
    uint32_t sb = smem_u32(smem);
    int tid = threadIdx.x, wid = tid >> 5, lane = tid & 31;
    int wm = wid & 1, wn = wid >> 1;

    const __nv_bfloat16* w2b_e = g_w2b + (size_t)e * HDIM * FDIM;
    const __nv_bfloat16* w2s_e = g_w2s + (size_t)e * HDIM * FDIM;

    float acc[4][4][4];
#pragma unroll
    for (int m = 0; m < 4; m++)
#pragma unroll
        for (int j = 0; j < 4; j++)
#pragma unroll
            for (int q = 0; q < 4; q++) acc[m][j][q] = 0.0f;

    const int NC = FDIM / 32;

    int r8 = lane & 7;
    uint32_t rowA_l = (uint32_t)(((lane >> 3) & 1) * 8 + r8);
    uint32_t kAb    = (uint32_t)(((lane >> 4) & 1) * 16);
    uint32_t nB_l   = (uint32_t)(((lane >> 4) & 1) * 8 + r8);
    uint32_t kBb    = (uint32_t)(((lane >> 3) & 1) * 16);

    auto loadg = [&](int cn) {
        int k0 = cn * 32;
        uint32_t st = sb + (cn % G2_STAGES) * G2_STAGEB;
#pragma unroll
        for (int i = 0; i < 8; i++) {       // A: 2 planes x 128 rows x 4
            int idx2 = tid + i * 128;
            int c16 = idx2 & 3, plane = (idx2 >> 2) & 1, row = idx2 >> 3;
            uint32_t dst = st + plane * APL + SW64B((uint32_t)(row * 64 + c16 * 16));
            const __nv_bfloat16* src = (plane ? g_hs : g_hb)
                + ((size_t)(row0 + row) * FDIM + k0 + c16 * 8);
            cpa16(dst, src, 16);
        }
#pragma unroll
        for (int i = 0; i < 4; i++) {       // B: 2 planes x 64 rows x 4
            int idx2 = tid + i * 128;
            int c16 = idx2 & 3, plane = (idx2 >> 2) & 1, row = idx2 >> 3;
            uint32_t dst = st + 2 * APL + plane * BPL + SW64B((uint32_t)(row * 64 + c16 * 16));
            const __nv_bfloat16* src = (plane ? w2s_e : w2b_e)
                + ((size_t)(n0 + row) * FDIM + k0 + c16 * 8);
            cpa16(dst, src, 16);
        }
        CP_COMMIT();
    };

    loadg(0); loadg(1); loadg(2);
    for (int c = 0; c < NC; c++) {
        if (c + 3 < NC) { CP_WAIT2(); } else { CP_WAIT0(); }
        __syncthreads();
        if (c + 3 < NC) loadg(c + 3);
        uint32_t st = sb + (c % G2_STAGES) * G2_STAGEB;
#pragma unroll
        for (int kk = 0; kk < 2; kk++) {
            uint32_t Ab[4][4], As[4][4];
#pragma unroll
            for (int mb = 0; mb < 4; mb++) {
                uint32_t off = SW64B((uint32_t)((wm * 64 + mb * 16 + rowA_l) * 64 + kk * 32 + kAb));
                ldm4(st + off, Ab[mb]);
                ldm4(st + APL + off, As[mb]);
            }
#pragma unroll
            for (int jp = 0; jp < 2; jp++) {
                uint32_t boff = SW64B((uint32_t)((wn * 32 + jp * 16 + nB_l) * 64 + kk * 32 + kBb));
                uint32_t bb = st + 2 * APL + boff;
                uint32_t Bb[4], Bs[4];
                ldm4(bb,       Bb);
                ldm4(bb + BPL, Bs);
                int j0 = jp * 2;
#pragma unroll
                for (int mb = 0; mb < 4; mb++) {
                    mma16816(acc[mb][j0],   Ab[mb], Bb[0], Bb[1]);
                    mma16816(acc[mb][j0+1], Ab[mb], Bb[2], Bb[3]);
                }
#pragma unroll
                for (int mb = 0; mb < 4; mb++) {
                    mma16816(acc[mb][j0],   Ab[mb], Bs[0], Bs[1]);
                    mma16816(acc[mb][j0+1], Ab[mb], Bs[2], Bs[3]);
                }
#pragma unroll
                for (int mb = 0; mb < 4; mb++) {
                    mma16816(acc[mb][j0],   As[mb], Bb[0], Bb[1]);
                    mma16816(acc[mb][j0+1], As[mb], Bb[2], Bb[3]);
                }
            }
        }
    }

    // epilogue: weighted atomicAdd
#pragma unroll
    for (int mb = 0; mb < 4; mb++) {
        int rA = row0 + wm * 64 + mb * 16 + (lane >> 2);
        int rB = rA + 8;
        int tA = g_row_token[rA], tB = g_row_token[rB];
        float wA = g_row_weight[rA], wB = g_row_weight[rB];
#pragma unroll
        for (int j = 0; j < 4; j++) {
            int col = n0 + wn * 32 + j * 8 + (lane & 3) * 2;
            if (tA >= 0) {
                float* p = out + (size_t)tA * HDIM + col;
                atomicAdd(p + 0, acc[mb][j][0] * wA);
                atomicAdd(p + 1, acc[mb][j][1] * wA);
            }
            if (tB >= 0) {
                float* p = out + (size_t)tB * HDIM + col;
                atomicAdd(p + 0, acc[mb][j][2] * wB);
                atomicAdd(p + 1, acc[mb][j][3] * wB);
            }
        }
    }
}

// ---------------- launcher ----------------
extern "C" void kernel_launch(void* const* d_in, const int* in_sizes, int n_in,
                              void* d_out, int out_size) {
    const float* x      = (const float*)d_in[0];
    const float* gate_w = (const float*)d_in[1];
    const float* w1     = (const float*)d_in[2];
    const float* w2     = (const float*)d_in[3];
    const float* w3     = (const float*)d_in[4];
    float* out          = (float*)d_out;
    float* logits_out   = out + (size_t)OUT_ELEMS;
    (void)in_sizes; (void)n_in; (void)out_size;

    const int smem1 = G1_STAGES * G1_STAGEB;   // 98304
    const int smem2 = G2_STAGES * G2_STAGEB;   // 98304
    cudaFuncSetAttribute(gemm1_mma, cudaFuncAttributeMaxDynamicSharedMemorySize, smem1);
    cudaFuncSetAttribute(gemm2_mma, cudaFuncAttributeMaxDynamicSharedMemorySize, smem2);

    init_kernel<<<(OUT_ELEMS + 255) / 256, 256>>>(out);
    {
        int n4w = (int)(WELEMS / 4);
        dim3 gw((n4w + 255) / 256, 3);
        split_w_kernel<<<gw, 256>>>(w1, w2, w3);
        split_x_kernel<<<(T_TOK * HDIM / 4 + 255) / 256, 256>>>(x);
    }
    router_kernel<<<T_TOK / 8, 256>>>(x, gate_w, logits_out);
    scan_kernel<<<1, 1>>>();
    scatter_kernel<<<(T_TOK + 255) / 256, 256>>>();

    // swizzled 1D grids (ROWS_MAX/BM = 136 m-tiles exactly divisible by group sizes)
    gemm1_mma<<<(ROWS_MAX / BM) * G1_NN, 128, smem1>>>();
    gemm2_mma<<<(ROWS_MAX / BM) * G2_NN, 128, smem2>>>(out);
}

// round 15
// speedup vs baseline: 1.4906x; 1.4132x over previous
#include <cuda_runtime.h>
#include <cuda_fp16.h>
#include <math.h>
#include <stdint.h>

// Problem constants
#define T_TOK 8192
#define HDIM  1024
#define FDIM  3584
#define NEXP  8
#define TOPK  2
#define BM    128
#define ROWS_MAX (T_TOK*TOPK + NEXP*BM)   // 17408
#define OUT_ELEMS (T_TOK*HDIM)

// smem geometry: fp16, 64B rows (32 elems), SW64 swizzle
#define APL    8192                  // 128 rows * 64 B (A plane)
#define BPL    4096                  // 64 rows * 64 B  (B plane)
#define G1_STAGEB (2*APL + 2*BPL)    // 24576 (Ab, As, B1, B3)
#define G2_STAGEB (2*APL + 1*BPL)    // 20480 (Ab, As, B)
#define G1_STAGES 4
#define G2_STAGES 4
#define SW64B(o) ((o) ^ (((o) >> 3) & 0x30))

#define WELEMS ((size_t)NEXP*FDIM*HDIM)   // 29,360,128

// ---------------- device scratch ----------------
__device__ __half g_w1h[WELEMS], g_w3h[WELEMS], g_w2h[WELEMS];
__device__ __half g_xb[(size_t)T_TOK*HDIM], g_xs[(size_t)T_TOK*HDIM];
__device__ __half g_hb[(size_t)ROWS_MAX*FDIM], g_hs[(size_t)ROWS_MAX*FDIM];
__device__ int   g_row_token[ROWS_MAX];
__device__ float g_row_weight[ROWS_MAX];
__device__ int   g_counts[NEXP];
__device__ int   g_offsets[NEXP + 1];
__device__ int   g_cursor[NEXP];
__device__ int   g_total_rows;
__device__ int   g_tok_expert[T_TOK * TOPK];
__device__ float g_tok_weight[T_TOK * TOPK];

// ---------------- helpers ----------------
__device__ __forceinline__ uint32_t smem_u32(const void* p) {
    uint32_t a;
    asm("{ .reg .u64 t; cvta.to.shared.u64 t, %1; cvt.u32.u64 %0, t; }" : "=r"(a) : "l"(p));
    return a;
}
__device__ __forceinline__ uint32_t pack2h(float x, float y) {
    __half2 t = __floats2half2_rn(x, y);
    return *(uint32_t*)&t;
}
__device__ __forceinline__ void split1h(float v, float& b, float& s) {
    __half hb = __float2half_rn(v);
    b = __half2float(hb);
    s = v - b;
}
__device__ __forceinline__ void mma16816(float (&d)[4], const uint32_t (&a)[4],
                                         uint32_t b0, uint32_t b1) {
    asm volatile(
        "mma.sync.aligned.m16n8k16.row.col.f32.f16.f16.f32 "
        "{%0,%1,%2,%3}, {%4,%5,%6,%7}, {%8,%9}, {%0,%1,%2,%3};"
        : "+f"(d[0]), "+f"(d[1]), "+f"(d[2]), "+f"(d[3])
        : "r"(a[0]), "r"(a[1]), "r"(a[2]), "r"(a[3]), "r"(b0), "r"(b1));
}
__device__ __forceinline__ void ldm4(uint32_t addr, uint32_t (&r)[4]) {
    asm volatile("ldmatrix.sync.aligned.m8n8.x4.shared.b16 {%0,%1,%2,%3}, [%4];"
                 : "=r"(r[0]), "=r"(r[1]), "=r"(r[2]), "=r"(r[3]) : "r"(addr));
}
__device__ __forceinline__ void cpa16(uint32_t dst, const void* src, int sz) {
    asm volatile("cp.async.cg.shared.global [%0], [%1], 16, %2;"
                 :: "r"(dst), "l"(src), "r"(sz) : "memory");
}
#define CP_COMMIT() asm volatile("cp.async.commit_group;" ::: "memory")
#define CP_WAIT2()  asm volatile("cp.async.wait_group 2;" ::: "memory")
#define CP_WAIT0()  asm volatile("cp.async.wait_group 0;" ::: "memory")

// ---------------- 0) init ----------------
__global__ void init_kernel(float* __restrict__ out) {
    int i = blockIdx.x * blockDim.x + threadIdx.x;
    if (i < OUT_ELEMS) out[i] = 0.0f;
    if (i < ROWS_MAX) { g_row_token[i] = -1; g_row_weight[i] = 0.0f; }
    if (i < NEXP) g_counts[i] = 0;
}

// ---------------- 0b) preconvert ----------------
__global__ void split_w_kernel(const float* __restrict__ w1,
                               const float* __restrict__ w2,
                               const float* __restrict__ w3) {
    int i = blockIdx.x * blockDim.x + threadIdx.x;
    const int N4 = (int)(WELEMS / 4);
    if (i >= N4) return;
    const float* src; __half* dh;
    if (blockIdx.y == 0)      { src = w1; dh = g_w1h; }
    else if (blockIdx.y == 1) { src = w3; dh = g_w3h; }
    else                      { src = w2; dh = g_w2h; }
    float4 v = ((const float4*)src)[i];
    ((uint2*)dh)[i] = make_uint2(pack2h(v.x, v.y), pack2h(v.z, v.w));
}
__global__ void split_x_kernel(const float* __restrict__ x) {
    int i = blockIdx.x * blockDim.x + threadIdx.x;
    const int N4 = T_TOK * HDIM / 4;
    if (i >= N4) return;
    float4 v = ((const float4*)x)[i];
    float b0,s0,b1,s1,b2,s2,b3,s3;
    split1h(v.x,b0,s0); split1h(v.y,b1,s1); split1h(v.z,b2,s2); split1h(v.w,b3,s3);
    ((uint2*)g_xb)[i] = make_uint2(pack2h(b0,b1), pack2h(b2,b3));
    ((uint2*)g_xs)[i] = make_uint2(pack2h(s0,s1), pack2h(s2,s3));
}

// ---------------- 1) router ----------------
__global__ void router_kernel(const float* __restrict__ x,
                              const float* __restrict__ gate_w,
                              float* __restrict__ logits_out) {
    __shared__ float s_gate[NEXP * HDIM];
    for (int i = threadIdx.x; i < NEXP * HDIM; i += blockDim.x)
        s_gate[i] = gate_w[i];
    __syncthreads();

    int warp = threadIdx.x >> 5, lane = threadIdx.x & 31;
    int t = blockIdx.x * (blockDim.x >> 5) + warp;
    if (t >= T_TOK) return;

    float acc[NEXP];
#pragma unroll
    for (int e = 0; e < NEXP; e++) acc[e] = 0.0f;
    const float* xr = x + (size_t)t * HDIM;
    for (int j = lane; j < HDIM; j += 32) {
        float xv = xr[j];
#pragma unroll
        for (int e = 0; e < NEXP; e++) acc[e] += xv * s_gate[e * HDIM + j];
    }
#pragma unroll
    for (int e = 0; e < NEXP; e++) {
#pragma unroll
        for (int o = 16; o > 0; o >>= 1)
            acc[e] += __shfl_xor_sync(0xffffffffu, acc[e], o);
    }
    if (lane == 0) {
        float mx = acc[0];
#pragma unroll
        for (int e = 1; e < NEXP; e++) mx = fmaxf(mx, acc[e]);
        float p[NEXP], s = 0.0f;
#pragma unroll
        for (int e = 0; e < NEXP; e++) { p[e] = expf(acc[e] - mx); s += p[e]; }
        float inv = 1.0f / s;
#pragma unroll
        for (int e = 0; e < NEXP; e++) p[e] *= inv;
        int i0 = 0;
#pragma unroll
        for (int e = 1; e < NEXP; e++) if (p[e] > p[i0]) i0 = e;
        int i1 = (i0 == 0) ? 1 : 0;
#pragma unroll
        for (int e = 0; e < NEXP; e++) if (e != i0 && p[e] > p[i1]) i1 = e;
        float w0 = p[i0], w1 = p[i1], ws = 1.0f / (w0 + w1);
        w0 *= ws; w1 *= ws;
#pragma unroll
        for (int e = 0; e < NEXP; e++) logits_out[(size_t)t * NEXP + e] = acc[e];
        g_tok_expert[t * 2 + 0] = i0; g_tok_expert[t * 2 + 1] = i1;
        g_tok_weight[t * 2 + 0] = w0; g_tok_weight[t * 2 + 1] = w1;
        atomicAdd(&g_counts[i0], 1);
        atomicAdd(&g_counts[i1], 1);
    }
}

// ---------------- 2) scan ----------------
__global__ void scan_kernel() {
    int total = 0;
    for (int e = 0; e < NEXP; e++) {
        g_offsets[e] = total;
        g_cursor[e]  = total;
        int padded = ((g_counts[e] + BM - 1) / BM) * BM;
        total += padded;
    }
    g_offsets[NEXP] = total;
    g_total_rows = total;
}

// ---------------- 3) scatter ----------------
__global__ void scatter_kernel() {
    int t = blockIdx.x * blockDim.x + threadIdx.x;
    if (t >= T_TOK) return;
#pragma unroll
    for (int s = 0; s < TOPK; s++) {
        int e = g_tok_expert[t * 2 + s];
        int p = atomicAdd(&g_cursor[e], 1);
        g_row_token[p]  = t;
        g_row_weight[p] = g_tok_weight[t * 2 + s];
    }
}

// ---------------- 4) GEMM1: 4 warps 64x32, 4-stage, fp16 2-term -----------------
__global__ __launch_bounds__(128, 2)
void gemm1_mma() {
    int row0 = blockIdx.x * BM;
    if (row0 >= g_total_rows) return;
    int n0 = blockIdx.y * 64;

    int e = 0;
#pragma unroll
    for (int i = 0; i < NEXP; i++) if (row0 >= g_offsets[i + 1]) e = i + 1;

    extern __shared__ char smem[];
    uint32_t sb = smem_u32(smem);
    int tid = threadIdx.x, wid = tid >> 5, lane = tid & 31;
    int wm = wid & 1, wn = wid >> 1;          // warp 64x32 on 128x64 CTA

    const __half* w1e = g_w1h + (size_t)e * FDIM * HDIM;
    const __half* w3e = g_w3h + (size_t)e * FDIM * HDIM;

    int tokc[8];
#pragma unroll
    for (int i = 0; i < 8; i++) tokc[i] = g_row_token[row0 + ((tid + i * 128) >> 3)];

    float acc1[4][4][4], acc3[4][4][4];
#pragma unroll
    for (int m = 0; m < 4; m++)
#pragma unroll
        for (int j = 0; j < 4; j++)
#pragma unroll
            for (int q = 0; q < 4; q++) { acc1[m][j][q] = 0.0f; acc3[m][j][q] = 0.0f; }

    const int NC = HDIM / 32;

    int r8 = lane & 7;
    uint32_t rowA_l = (uint32_t)(((lane >> 3) & 1) * 8 + r8);
    uint32_t kAb    = (uint32_t)(((lane >> 4) & 1) * 16);
    uint32_t nB_l   = (uint32_t)(((lane >> 4) & 1) * 8 + r8);
    uint32_t kBb    = (uint32_t)(((lane >> 3) & 1) * 16);

    auto loadg = [&](int cn) {
        int k0 = cn * 32;
        uint32_t st = sb + (cn % G1_STAGES) * G1_STAGEB;
#pragma unroll
        for (int i = 0; i < 8; i++) {       // A: 2 planes x 128 rows x 4
            int idx2 = tid + i * 128;
            int c16 = idx2 & 3, plane = (idx2 >> 2) & 1, row = idx2 >> 3;
            uint32_t dst = st + plane * APL + SW64B((uint32_t)(row * 64 + c16 * 16));
            int t = tokc[i];
            const __half* src = (plane ? g_xs : g_xb)
                + ((size_t)(t < 0 ? 0 : t) * HDIM + k0 + c16 * 8);
            cpa16(dst, src, t < 0 ? 0 : 16);
        }
#pragma unroll
        for (int i = 0; i < 4; i++) {       // B: 2 planes (w1,w3) x 64 rows x 4
            int idx2 = tid + i * 128;
            int c16 = idx2 & 3, plane = (idx2 >> 2) & 1, row = idx2 >> 3;
            uint32_t dst = st + 2 * APL + plane * BPL + SW64B((uint32_t)(row * 64 + c16 * 16));
            const __half* src = (plane ? w3e : w1e)
                + ((size_t)(n0 + row) * HDIM + k0 + c16 * 8);
            cpa16(dst, src, 16);
        }
        CP_COMMIT();
    };

    loadg(0); loadg(1); loadg(2);
    for (int c = 0; c < NC; c++) {
        if (c + 3 < NC) { CP_WAIT2(); } else { CP_WAIT0(); }
        __syncthreads();
        if (c + 3 < NC) loadg(c + 3);
        uint32_t st = sb + (c % G1_STAGES) * G1_STAGEB;
#pragma unroll
        for (int kk = 0; kk < 2; kk++) {
            uint32_t Ab[4][4], As[4][4];
#pragma unroll
            for (int mb = 0; mb < 4; mb++) {
                uint32_t off = SW64B((uint32_t)((wm * 64 + mb * 16 + rowA_l) * 64 + kk * 32 + kAb));
                ldm4(st + off, Ab[mb]);
                ldm4(st + APL + off, As[mb]);
            }
#pragma unroll
            for (int jp = 0; jp < 2; jp++) {
                uint32_t boff = SW64B((uint32_t)((wn * 32 + jp * 16 + nB_l) * 64 + kk * 32 + kBb));
                uint32_t bb = st + 2 * APL + boff;
                uint32_t B1[4], B3[4];
                ldm4(bb,       B1);
                ldm4(bb + BPL, B3);
                int j0 = jp * 2;
#pragma unroll
                for (int mb = 0; mb < 4; mb++) {
                    mma16816(acc1[mb][j0],   Ab[mb], B1[0], B1[1]);
                    mma16816(acc1[mb][j0+1], Ab[mb], B1[2], B1[3]);
                    mma16816(acc3[mb][j0],   Ab[mb], B3[0], B3[1]);
                    mma16816(acc3[mb][j0+1], Ab[mb], B3[2], B3[3]);
                }
#pragma unroll
                for (int mb = 0; mb < 4; mb++) {
                    mma16816(acc1[mb][j0],   As[mb], B1[0], B1[1]);
                    mma16816(acc1[mb][j0+1], As[mb], B1[2], B1[3]);
                    mma16816(acc3[mb][j0],   As[mb], B3[0], B3[1]);
                    mma16816(acc3[mb][j0+1], As[mb], B3[2], B3[3]);
                }
            }
        }
    }

    // epilogue: h = silu(g)*u -> fp16 big/small planes
#pragma unroll
    for (int mb = 0; mb < 4; mb++) {
        int rA = row0 + wm * 64 + mb * 16 + (lane >> 2);
        int rB = rA + 8;
#pragma unroll
        for (int j = 0; j < 4; j++) {
            int col = n0 + wn * 32 + j * 8 + (lane & 3) * 2;
            float g0 = acc1[mb][j][0], g1 = acc1[mb][j][1];
            float g2 = acc1[mb][j][2], g3 = acc1[mb][j][3];
            float u0 = acc3[mb][j][0], u1 = acc3[mb][j][1];
            float u2 = acc3[mb][j][2], u3 = acc3[mb][j][3];
            float h0 = g0 / (1.0f + __expf(-g0)) * u0;
            float h1 = g1 / (1.0f + __expf(-g1)) * u1;
            float h2 = g2 / (1.0f + __expf(-g2)) * u2;
            float h3 = g3 / (1.0f + __expf(-g3)) * u3;
            float b0,s0,b1,s1;
            split1h(h0, b0, s0); split1h(h1, b1, s1);
            *(uint32_t*)(g_hb + (size_t)rA * FDIM + col) = pack2h(b0, b1);
            *(uint32_t*)(g_hs + (size_t)rA * FDIM + col) = pack2h(s0, s1);
            split1h(h2, b0, s0); split1h(h3, b1, s1);
            *(uint32_t*)(g_hb + (size_t)rB * FDIM + col) = pack2h(b0, b1);
            *(uint32_t*)(g_hs + (size_t)rB * FDIM + col) = pack2h(s0, s1);
        }
    }
}

// ---------------- 5) GEMM2: 4 warps 64x32, 4-stage, fp16 2-term -----------------
__global__ __launch_bounds__(128, 2)
void gemm2_mma(float* __restrict__ out) {
    int row0 = blockIdx.x * BM;
    if (row0 >= g_total_rows) return;
    int n0 = blockIdx.y * 64;

    int e = 0;
#pragma unroll
    for (int i = 0; i < NEXP; i++) if (row0 >= g_offsets[i + 1]) e = i + 1;

    extern __shared__ char smem[];
    uint32_t sb = smem_u32(smem);
    int tid = threadIdx.x, wid = tid >> 5, lane = tid & 31;
    int wm = wid & 1, wn = wid >> 1;

    const __half* w2e = g_w2h + (size_t)e * HDIM * FDIM;

    float acc[4][4][4];
#pragma unroll
    for (int m = 0; m < 4; m++)
#pragma unroll
        for (int j = 0; j < 4; j++)
#pragma unroll
            for (int q = 0; q < 4; q++) acc[m][j][q] = 0.0f;

    const int NC = FDIM / 32;

    int r8 = lane & 7;
    uint32_t rowA_l = (uint32_t)(((lane >> 3) & 1) * 8 + r8);
    uint32_t kAb    = (uint32_t)(((lane >> 4) & 1) * 16);
    uint32_t nB_l   = (uint32_t)(((lane >> 4) & 1) * 8 + r8);
    uint32_t kBb    = (uint32_t)(((lane >> 3) & 1) * 16);

    auto loadg = [&](int cn) {
        int k0 = cn * 32;
        uint32_t st = sb + (cn % G2_STAGES) * G2_STAGEB;
#pragma unroll
        for (int i = 0; i < 8; i++) {       // A: 2 planes x 128 rows x 4
            int idx2 = tid + i * 128;
            int c16 = idx2 & 3, plane = (idx2 >> 2) & 1, row = idx2 >> 3;
            uint32_t dst = st + plane * APL + SW64B((uint32_t)(row * 64 + c16 * 16));
            const __half* src = (plane ? g_hs : g_hb)
                + ((size_t)(row0 + row) * FDIM + k0 + c16 * 8);
            cpa16(dst, src, 16);
        }
#pragma unroll
        for (int i = 0; i < 2; i++) {       // B: 1 plane x 64 rows x 4
            int idx2 = tid + i * 128;
            int c16 = idx2 & 3, row = idx2 >> 2;
            uint32_t dst = st + 2 * APL + SW64B((uint32_t)(row * 64 + c16 * 16));
            cpa16(dst, w2e + ((size_t)(n0 + row) * FDIM + k0 + c16 * 8), 16);
        }
        CP_COMMIT();
    };

    loadg(0); loadg(1); loadg(2);
    for (int c = 0; c < NC; c++) {
        if (c + 3 < NC) { CP_WAIT2(); } else { CP_WAIT0(); }
        __syncthreads();
        if (c + 3 < NC) loadg(c + 3);
        uint32_t st = sb + (c % G2_STAGES) * G2_STAGEB;
#pragma unroll
        for (int kk = 0; kk < 2; kk++) {
            uint32_t Ab[4][4], As[4][4];
#pragma unroll
            for (int mb = 0; mb < 4; mb++) {
                uint32_t off = SW64B((uint32_t)((wm * 64 + mb * 16 + rowA_l) * 64 + kk * 32 + kAb));
                ldm4(st + off, Ab[mb]);
                ldm4(st + APL + off, As[mb]);
            }
#pragma unroll
            for (int jp = 0; jp < 2; jp++) {
                uint32_t boff = SW64B((uint32_t)((wn * 32 + jp * 16 + nB_l) * 64 + kk * 32 + kBb));
                uint32_t bb = st + 2 * APL + boff;
                uint32_t B[4];
                ldm4(bb, B);
                int j0 = jp * 2;
#pragma unroll
                for (int mb = 0; mb < 4; mb++) {
                    mma16816(acc[mb][j0],   Ab[mb], B[0], B[1]);
                    mma16816(acc[mb][j0+1], Ab[mb], B[2], B[3]);
                }
#pragma unroll
                for (int mb = 0; mb < 4; mb++) {
                    mma16816(acc[mb][j0],   As[mb], B[0], B[1]);
                    mma16816(acc[mb][j0+1], As[mb], B[2], B[3]);
                }
            }
        }
    }

    // epilogue: weighted atomicAdd
#pragma unroll
    for (int mb = 0; mb < 4; mb++) {
        int rA = row0 + wm * 64 + mb * 16 + (lane >> 2);
        int rB = rA + 8;
        int tA = g_row_token[rA], tB = g_row_token[rB];
        float wA = g_row_weight[rA], wB = g_row_weight[rB];
#pragma unroll
        for (int j = 0; j < 4; j++) {
            int col = n0 + wn * 32 + j * 8 + (lane & 3) * 2;
            if (tA >= 0) {
                float* p = out + (size_t)tA * HDIM + col;
                atomicAdd(p + 0, acc[mb][j][0] * wA);
                atomicAdd(p + 1, acc[mb][j][1] * wA);
            }
            if (tB >= 0) {
                float* p = out + (size_t)tB * HDIM + col;
                atomicAdd(p + 0, acc[mb][j][2] * wB);
                atomicAdd(p + 1, acc[mb][j][3] * wB);
            }
        }
    }
}

// ---------------- launcher ----------------
extern "C" void kernel_launch(void* const* d_in, const int* in_sizes, int n_in,
                              void* d_out, int out_size) {
    const float* x      = (const float*)d_in[0];
    const float* gate_w = (const float*)d_in[1];
    const float* w1     = (const float*)d_in[2];
    const float* w2     = (const float*)d_in[3];
    const float* w3     = (const float*)d_in[4];
    float* out          = (float*)d_out;
    float* logits_out   = out + (size_t)OUT_ELEMS;
    (void)in_sizes; (void)n_in; (void)out_size;

    const int smem1 = G1_STAGES * G1_STAGEB;   // 98304
    const int smem2 = G2_STAGES * G2_STAGEB;   // 81920
    cudaFuncSetAttribute(gemm1_mma, cudaFuncAttributeMaxDynamicSharedMemorySize, smem1);
    cudaFuncSetAttribute(gemm2_mma, cudaFuncAttributeMaxDynamicSharedMemorySize, smem2);

    init_kernel<<<(OUT_ELEMS + 255) / 256, 256>>>(out);
    {
        int n4w = (int)(WELEMS / 4);
        dim3 gw((n4w + 255) / 256, 3);
        split_w_kernel<<<gw, 256>>>(w1, w2, w3);
        split_x_kernel<<<(T_TOK * HDIM / 4 + 255) / 256, 256>>>(x);
    }
    router_kernel<<<T_TOK / 8, 256>>>(x, gate_w, logits_out);
    scan_kernel<<<1, 1>>>();
    scatter_kernel<<<(T_TOK + 255) / 256, 256>>>();

    dim3 g1(ROWS_MAX / BM, FDIM / 64);
    gemm1_mma<<<g1, 128, smem1>>>();
    dim3 g2(ROWS_MAX / BM, HDIM / 64);
    gemm2_mma<<<g2, 128, smem2>>>(out);
}

// round 16
// speedup vs baseline: 2.7243x; 1.8276x over previous
#include <cuda_runtime.h>
#include <cuda_fp16.h>
#include <math.h>
#include <stdint.h>

// Problem constants
#define T_TOK 8192
#define HDIM  1024
#define FDIM  3584
#define NEXP  8
#define TOPK  2
#define BM    128
#define ROWS_MAX (T_TOK*TOPK + NEXP*BM)   // 17408
#define OUT_ELEMS (T_TOK*HDIM)

// smem geometry: fp16, 64B rows (32 elems), SW64 swizzle
#define APL    8192                  // 128 rows * 64 B (A plane)
#define BPL    4096                  // 64 rows * 64 B  (B plane)
#define G1_STAGEB (APL + 2*BPL)      // 16384 (A, B1, B3)
#define G2_STAGEB (APL + 1*BPL)      // 12288 (A, B)
#define G1_STAGES 4
#define G2_STAGES 4
#define SW64B(o) ((o) ^ (((o) >> 3) & 0x30))

#define WELEMS ((size_t)NEXP*FDIM*HDIM)   // 29,360,128

// ---------------- device scratch ----------------
__device__ __half g_w1h[WELEMS], g_w3h[WELEMS], g_w2h[WELEMS];
__device__ __half g_xh[(size_t)T_TOK*HDIM];
__device__ __half g_hh[(size_t)ROWS_MAX*FDIM];
__device__ int   g_row_token[ROWS_MAX];
__device__ float g_row_weight[ROWS_MAX];
__device__ int   g_counts[NEXP];
__device__ int   g_offsets[NEXP + 1];
__device__ int   g_cursor[NEXP];
__device__ int   g_total_rows;
__device__ int   g_tok_expert[T_TOK * TOPK];
__device__ float g_tok_weight[T_TOK * TOPK];

// ---------------- helpers ----------------
__device__ __forceinline__ uint32_t smem_u32(const void* p) {
    uint32_t a;
    asm("{ .reg .u64 t; cvta.to.shared.u64 t, %1; cvt.u32.u64 %0, t; }" : "=r"(a) : "l"(p));
    return a;
}
__device__ __forceinline__ uint32_t pack2h(float x, float y) {
    __half2 t = __floats2half2_rn(x, y);
    return *(uint32_t*)&t;
}
__device__ __forceinline__ void mma16816(float (&d)[4], const uint32_t (&a)[4],
                                         uint32_t b0, uint32_t b1) {
    asm volatile(
        "mma.sync.aligned.m16n8k16.row.col.f32.f16.f16.f32 "
        "{%0,%1,%2,%3}, {%4,%5,%6,%7}, {%8,%9}, {%0,%1,%2,%3};"
        : "+f"(d[0]), "+f"(d[1]), "+f"(d[2]), "+f"(d[3])
        : "r"(a[0]), "r"(a[1]), "r"(a[2]), "r"(a[3]), "r"(b0), "r"(b1));
}
__device__ __forceinline__ void ldm4(uint32_t addr, uint32_t (&r)[4]) {
    asm volatile("ldmatrix.sync.aligned.m8n8.x4.shared.b16 {%0,%1,%2,%3}, [%4];"
                 : "=r"(r[0]), "=r"(r[1]), "=r"(r[2]), "=r"(r[3]) : "r"(addr));
}
__device__ __forceinline__ void cpa16(uint32_t dst, const void* src, int sz) {
    asm volatile("cp.async.cg.shared.global [%0], [%1], 16, %2;"
                 :: "r"(dst), "l"(src), "r"(sz) : "memory");
}
#define CP_COMMIT() asm volatile("cp.async.commit_group;" ::: "memory")
#define CP_WAIT2()  asm volatile("cp.async.wait_group 2;" ::: "memory")
#define CP_WAIT0()  asm volatile("cp.async.wait_group 0;" ::: "memory")

// ---------------- 0) init ----------------
__global__ void init_kernel(float* __restrict__ out) {
    int i = blockIdx.x * blockDim.x + threadIdx.x;
    if (i < OUT_ELEMS) out[i] = 0.0f;
    if (i < ROWS_MAX) { g_row_token[i] = -1; g_row_weight[i] = 0.0f; }
    if (i < NEXP) g_counts[i] = 0;
}

// ---------------- 0b) preconvert fp32 -> fp16 ----------------
__global__ void conv_w_kernel(const float* __restrict__ w1,
                              const float* __restrict__ w2,
                              const float* __restrict__ w3) {
    int i = blockIdx.x * blockDim.x + threadIdx.x;
    const int N4 = (int)(WELEMS / 4);
    if (i >= N4) return;
    const float* src; __half* dh;
    if (blockIdx.y == 0)      { src = w1; dh = g_w1h; }
    else if (blockIdx.y == 1) { src = w3; dh = g_w3h; }
    else                      { src = w2; dh = g_w2h; }
    float4 v = ((const float4*)src)[i];
    ((uint2*)dh)[i] = make_uint2(pack2h(v.x, v.y), pack2h(v.z, v.w));
}
__global__ void conv_x_kernel(const float* __restrict__ x) {
    int i = blockIdx.x * blockDim.x + threadIdx.x;
    const int N4 = T_TOK * HDIM / 4;
    if (i >= N4) return;
    float4 v = ((const float4*)x)[i];
    ((uint2*)g_xh)[i] = make_uint2(pack2h(v.x, v.y), pack2h(v.z, v.w));
}

// ---------------- 1) router ----------------
__global__ void router_kernel(const float* __restrict__ x,
                              const float* __restrict__ gate_w,
                              float* __restrict__ logits_out) {
    __shared__ float s_gate[NEXP * HDIM];
    for (int i = threadIdx.x; i < NEXP * HDIM; i += blockDim.x)
        s_gate[i] = gate_w[i];
    __syncthreads();

    int warp = threadIdx.x >> 5, lane = threadIdx.x & 31;
    int t = blockIdx.x * (blockDim.x >> 5) + warp;
    if (t >= T_TOK) return;

    float acc[NEXP];
#pragma unroll
    for (int e = 0; e < NEXP; e++) acc[e] = 0.0f;
    const float* xr = x + (size_t)t * HDIM;
    for (int j = lane; j < HDIM; j += 32) {
        float xv = xr[j];
#pragma unroll
        for (int e = 0; e < NEXP; e++) acc[e] += xv * s_gate[e * HDIM + j];
    }
#pragma unroll
    for (int e = 0; e < NEXP; e++) {
#pragma unroll
        for (int o = 16; o > 0; o >>= 1)
            acc[e] += __shfl_xor_sync(0xffffffffu, acc[e], o);
    }
    if (lane == 0) {
        float mx = acc[0];
#pragma unroll
        for (int e = 1; e < NEXP; e++) mx = fmaxf(mx, acc[e]);
        float p[NEXP], s = 0.0f;
#pragma unroll
        for (int e = 0; e < NEXP; e++) { p[e] = expf(acc[e] - mx); s += p[e]; }
        float inv = 1.0f / s;
#pragma unroll
        for (int e = 0; e < NEXP; e++) p[e] *= inv;
        int i0 = 0;
#pragma unroll
        for (int e = 1; e < NEXP; e++) if (p[e] > p[i0]) i0 = e;
        int i1 = (i0 == 0) ? 1 : 0;
#pragma unroll
        for (int e = 0; e < NEXP; e++) if (e != i0 && p[e] > p[i1]) i1 = e;
        float w0 = p[i0], w1 = p[i1], ws = 1.0f / (w0 + w1);
        w0 *= ws; w1 *= ws;
#pragma unroll
        for (int e = 0; e < NEXP; e++) logits_out[(size_t)t * NEXP + e] = acc[e];
        g_tok_expert[t * 2 + 0] = i0; g_tok_expert[t * 2 + 1] = i1;
        g_tok_weight[t * 2 + 0] = w0; g_tok_weight[t * 2 + 1] = w1;
        atomicAdd(&g_counts[i0], 1);
        atomicAdd(&g_counts[i1], 1);
    }
}

// ---------------- 2) scan ----------------
__global__ void scan_kernel() {
    int total = 0;
    for (int e = 0; e < NEXP; e++) {
        g_offsets[e] = total;
        g_cursor[e]  = total;
        int padded = ((g_counts[e] + BM - 1) / BM) * BM;
        total += padded;
    }
    g_offsets[NEXP] = total;
    g_total_rows = total;
}

// ---------------- 3) scatter ----------------
__global__ void scatter_kernel() {
    int t = blockIdx.x * blockDim.x + threadIdx.x;
    if (t >= T_TOK) return;
#pragma unroll
    for (int s = 0; s < TOPK; s++) {
        int e = g_tok_expert[t * 2 + s];
        int p = atomicAdd(&g_cursor[e], 1);
        g_row_token[p]  = t;
        g_row_weight[p] = g_tok_weight[t * 2 + s];
    }
}

// ---------------- 4) GEMM1: 4 warps 64x32, 4-stage, pure fp16 -------------------
__global__ __launch_bounds__(128, 2)
void gemm1_mma() {
    int row0 = blockIdx.x * BM;
    if (row0 >= g_total_rows) return;
    int n0 = blockIdx.y * 64;

    int e = 0;
#pragma unroll
    for (int i = 0; i < NEXP; i++) if (row0 >= g_offsets[i + 1]) e = i + 1;

    extern __shared__ char smem[];
    uint32_t sb = smem_u32(smem);
    int tid = threadIdx.x, wid = tid >> 5, lane = tid & 31;
    int wm = wid & 1, wn = wid >> 1;          // warp 64x32 on 128x64 CTA

    const __half* w1e = g_w1h + (size_t)e * FDIM * HDIM;
    const __half* w3e = g_w3h + (size_t)e * FDIM * HDIM;

    int tokc[4];
#pragma unroll
    for (int i = 0; i < 4; i++) tokc[i] = g_row_token[row0 + ((tid + i * 128) >> 2)];

    float acc1[4][4][4], acc3[4][4][4];
#pragma unroll
    for (int m = 0; m < 4; m++)
#pragma unroll
        for (int j = 0; j < 4; j++)
#pragma unroll
            for (int q = 0; q < 4; q++) { acc1[m][j][q] = 0.0f; acc3[m][j][q] = 0.0f; }

    const int NC = HDIM / 32;

    int r8 = lane & 7;
    uint32_t rowA_l = (uint32_t)(((lane >> 3) & 1) * 8 + r8);
    uint32_t kAb    = (uint32_t)(((lane >> 4) & 1) * 16);
    uint32_t nB_l   = (uint32_t)(((lane >> 4) & 1) * 8 + r8);
    uint32_t kBb    = (uint32_t)(((lane >> 3) & 1) * 16);

    auto loadg = [&](int cn) {
        int k0 = cn * 32;
        uint32_t st = sb + (cn % G1_STAGES) * G1_STAGEB;
#pragma unroll
        for (int i = 0; i < 4; i++) {       // A: 128 rows x 64B
            int idx2 = tid + i * 128;
            int c16 = idx2 & 3, row = idx2 >> 2;
            uint32_t dst = st + SW64B((uint32_t)(row * 64 + c16 * 16));
            int t = tokc[i];
            const __half* src = g_xh + ((size_t)(t < 0 ? 0 : t) * HDIM + k0 + c16 * 8);
            cpa16(dst, src, t < 0 ? 0 : 16);
        }
#pragma unroll
        for (int i = 0; i < 4; i++) {       // B: 2 planes (w1,w3) x 64 rows x 64B
            int idx2 = tid + i * 128;
            int c16 = idx2 & 3, plane = (idx2 >> 2) & 1, row = idx2 >> 3;
            uint32_t dst = st + APL + plane * BPL + SW64B((uint32_t)(row * 64 + c16 * 16));
            const __half* src = (plane ? w3e : w1e)
                + ((size_t)(n0 + row) * HDIM + k0 + c16 * 8);
            cpa16(dst, src, 16);
        }
        CP_COMMIT();
    };

    loadg(0); loadg(1); loadg(2);
    for (int c = 0; c < NC; c++) {
        if (c + 3 < NC) { CP_WAIT2(); } else { CP_WAIT0(); }
        __syncthreads();
        if (c + 3 < NC) loadg(c + 3);
        uint32_t st = sb + (c % G1_STAGES) * G1_STAGEB;
#pragma unroll
        for (int kk = 0; kk < 2; kk++) {
            uint32_t A[4][4];
#pragma unroll
            for (int mb = 0; mb < 4; mb++) {
                uint32_t off = SW64B((uint32_t)((wm * 64 + mb * 16 + rowA_l) * 64 + kk * 32 + kAb));
                ldm4(st + off, A[mb]);
            }
#pragma unroll
            for (int jp = 0; jp < 2; jp++) {
                uint32_t boff = SW64B((uint32_t)((wn * 32 + jp * 16 + nB_l) * 64 + kk * 32 + kBb));
                uint32_t bb = st + APL + boff;
                uint32_t B1[4], B3[4];
                ldm4(bb,       B1);
                ldm4(bb + BPL, B3);
                int j0 = jp * 2;
#pragma unroll
                for (int mb = 0; mb < 4; mb++) {
                    mma16816(acc1[mb][j0],   A[mb], B1[0], B1[1]);
                    mma16816(acc1[mb][j0+1], A[mb], B1[2], B1[3]);
                    mma16816(acc3[mb][j0],   A[mb], B3[0], B3[1]);
                    mma16816(acc3[mb][j0+1], A[mb], B3[2], B3[3]);
                }
            }
        }
    }

    // epilogue: h = silu(g)*u -> fp16
#pragma unroll
    for (int mb = 0; mb < 4; mb++) {
        int rA = row0 + wm * 64 + mb * 16 + (lane >> 2);
        int rB = rA + 8;
#pragma unroll
        for (int j = 0; j < 4; j++) {
            int col = n0 + wn * 32 + j * 8 + (lane & 3) * 2;
            float g0 = acc1[mb][j][0], g1 = acc1[mb][j][1];
            float g2 = acc1[mb][j][2], g3 = acc1[mb][j][3];
            float u0 = acc3[mb][j][0], u1 = acc3[mb][j][1];
            float u2 = acc3[mb][j][2], u3 = acc3[mb][j][3];
            float h0 = g0 / (1.0f + __expf(-g0)) * u0;
            float h1 = g1 / (1.0f + __expf(-g1)) * u1;
            float h2 = g2 / (1.0f + __expf(-g2)) * u2;
            float h3 = g3 / (1.0f + __expf(-g3)) * u3;
            *(uint32_t*)(g_hh + (size_t)rA * FDIM + col) = pack2h(h0, h1);
            *(uint32_t*)(g_hh + (size_t)rB * FDIM + col) = pack2h(h2, h3);
        }
    }
}

// ---------------- 5) GEMM2: 4 warps 64x32, 4-stage, pure fp16 -------------------
__global__ __launch_bounds__(128, 2)
void gemm2_mma(float* __restrict__ out) {
    int row0 = blockIdx.x * BM;
    if (row0 >= g_total_rows) return;
    int n0 = blockIdx.y * 64;

    int e = 0;
#pragma unroll
    for (int i = 0; i < NEXP; i++) if (row0 >= g_offsets[i + 1]) e = i + 1;

    extern __shared__ char smem[];
    uint32_t sb = smem_u32(smem);
    int tid = threadIdx.x, wid = tid >> 5, lane = tid & 31;
    int wm = wid & 1, wn = wid >> 1;

    const __half* w2e = g_w2h + (size_t)e * HDIM * FDIM;

    float acc[4][4][4];
#pragma unroll
    for (int m = 0; m < 4; m++)
#pragma unroll
        for (int j = 0; j < 4; j++)
#pragma unroll
            for (int q = 0; q < 4; q++) acc[m][j][q] = 0.0f;

    const int NC = FDIM / 32;

    int r8 = lane & 7;
    uint32_t rowA_l = (uint32_t)(((lane >> 3) & 1) * 8 + r8);
    uint32_t kAb    = (uint32_t)(((lane >> 4) & 1) * 16);
    uint32_t nB_l   = (uint32_t)(((lane >> 4) & 1) * 8 + r8);
    uint32_t kBb    = (uint32_t)(((lane >> 3) & 1) * 16);

    auto loadg = [&](int cn) {
        int k0 = cn * 32;
        uint32_t st = sb + (cn % G2_STAGES) * G2_STAGEB;
#pragma unroll
        for (int i = 0; i < 4; i++) {       // A: 128 rows x 64B
            int idx2 = tid + i * 128;
            int c16 = idx2 & 3, row = idx2 >> 2;
            uint32_t dst = st + SW64B((uint32_t)(row * 64 + c16 * 16));
            cpa16(dst, g_hh + ((size_t)(row0 + row) * FDIM + k0 + c16 * 8), 16);
        }
#pragma unroll
        for (int i = 0; i < 2; i++) {       // B: 64 rows x 64B
            int idx2 = tid + i * 128;
            int c16 = idx2 & 3, row = idx2 >> 2;
            uint32_t dst = st + APL + SW64B((uint32_t)(row * 64 + c16 * 16));
            cpa16(dst, w2e + ((size_t)(n0 + row) * FDIM + k0 + c16 * 8), 16);
        }
        CP_COMMIT();
    };

    loadg(0); loadg(1); loadg(2);
    for (int c = 0; c < NC; c++) {
        if (c + 3 < NC) { CP_WAIT2(); } else { CP_WAIT0(); }
        __syncthreads();
        if (c + 3 < NC) loadg(c + 3);
        uint32_t st = sb + (c % G2_STAGES) * G2_STAGEB;
#pragma unroll
        for (int kk = 0; kk < 2; kk++) {
            uint32_t A[4][4];
#pragma unroll
            for (int mb = 0; mb < 4; mb++) {
                uint32_t off = SW64B((uint32_t)((wm * 64 + mb * 16 + rowA_l) * 64 + kk * 32 + kAb));
                ldm4(st + off, A[mb]);
            }
#pragma unroll
            for (int jp = 0; jp < 2; jp++) {
                uint32_t boff = SW64B((uint32_t)((wn * 32 + jp * 16 + nB_l) * 64 + kk * 32 + kBb));
                uint32_t B[4];
                ldm4(st + APL + boff, B);
                int j0 = jp * 2;
#pragma unroll
                for (int mb = 0; mb < 4; mb++) {
                    mma16816(acc[mb][j0],   A[mb], B[0], B[1]);
                    mma16816(acc[mb][j0+1], A[mb], B[2], B[3]);
                }
            }
        }
    }

    // epilogue: weighted atomicAdd
#pragma unroll
    for (int mb = 0; mb < 4; mb++) {
        int rA = row0 + wm * 64 + mb * 16 + (lane >> 2);
        int rB = rA + 8;
        int tA = g_row_token[rA], tB = g_row_token[rB];
        float wA = g_row_weight[rA], wB = g_row_weight[rB];
#pragma unroll
        for (int j = 0; j < 4; j++) {
            int col = n0 + wn * 32 + j * 8 + (lane & 3) * 2;
            if (tA >= 0) {
                float* p = out + (size_t)tA * HDIM + col;
                atomicAdd(p + 0, acc[mb][j][0] * wA);
                atomicAdd(p + 1, acc[mb][j][1] * wA);
            }
            if (tB >= 0) {
                float* p = out + (size_t)tB * HDIM + col;
                atomicAdd(p + 0, acc[mb][j][2] * wB);
                atomicAdd(p + 1, acc[mb][j][3] * wB);
            }
        }
    }
}

// ---------------- launcher ----------------
extern "C" void kernel_launch(void* const* d_in, const int* in_sizes, int n_in,
                              void* d_out, int out_size) {
    const float* x      = (const float*)d_in[0];
    const float* gate_w = (const float*)d_in[1];
    const float* w1     = (const float*)d_in[2];
    const float* w2     = (const float*)d_in[3];
    const float* w3     = (const float*)d_in[4];
    float* out          = (float*)d_out;
    float* logits_out   = out + (size_t)OUT_ELEMS;
    (void)in_sizes; (void)n_in; (void)out_size;

    const int smem1 = G1_STAGES * G1_STAGEB;   // 65536
    const int smem2 = G2_STAGES * G2_STAGEB;   // 49152
    cudaFuncSetAttribute(gemm1_mma, cudaFuncAttributeMaxDynamicSharedMemorySize, smem1);
    cudaFuncSetAttribute(gemm2_mma, cudaFuncAttributeMaxDynamicSharedMemorySize, smem2);

    init_kernel<<<(OUT_ELEMS + 255) / 256, 256>>>(out);
    {
        int n4w = (int)(WELEMS / 4);
        dim3 gw((n4w + 255) / 256, 3);
        conv_w_kernel<<<gw, 256>>>(w1, w2, w3);
        conv_x_kernel<<<(T_TOK * HDIM / 4 + 255) / 256, 256>>>(x);
    }
    router_kernel<<<T_TOK / 8, 256>>>(x, gate_w, logits_out);
    scan_kernel<<<1, 1>>>();
    scatter_kernel<<<(T_TOK + 255) / 256, 256>>>();

    dim3 g1(ROWS_MAX / BM, FDIM / 64);
    gemm1_mma<<<g1, 128, smem1>>>();
    dim3 g2(ROWS_MAX / BM, HDIM / 64);
    gemm2_mma<<<g2, 128, smem2>>>(out);
}